// round 15
// baseline (speedup 1.0000x reference)
#include <cuda_runtime.h>
#include <math_constants.h>

#define NB 8
#define NP 4096
#define THREADS 256
#define ILX 4                        // scalar x-points per thread (duplicated-packed)
#define XCHUNK (THREADS * ILX)       // 1024
#define XC (NP / XCHUNK)             // 4
#define YT 256
#define YP (YT / 2)                  // 128 j-pairs
#define YC (NP / YT)                 // 16
#define NDB (2 * NB)                 // 16 (dir, batch) pairs
#define NBLOCKS (YC * XC * NDB)      // 1024
#define NKEY (NDB * NP)              // 65536

#define FMA_F32X2(d, a, b, c) \
    asm("fma.rn.f32x2 %0, %1, %2, %3;" : "=l"(d) : "l"(a), "l"(b), "l"(c))
#define PACK_F32X2(out, lo, hi) \
    asm("mov.b64 %0, {%1, %2};" : "=l"(out) : "f"(lo), "f"(hi))
#define UNPACK_F32X2(lo, hi, in) \
    asm("mov.b64 {%0, %1}, %2;" : "=f"(lo), "=f"(hi) : "l"(in))

// Per-(dir,batch,point) running min, as a transformed unsigned key where
// LARGER unsigned == SMALLER float, and 0 == "+inf". So atomicMax implements
// float-min and BSS zero-init is the correct initial state. The in-kernel
// final fold resets the slots to 0 after consuming them -> every graph
// replay sees the same initial state (deterministic, no init kernel).
__device__ unsigned int g_min[NKEY];        // 256 KB
__device__ int g_count;                     // reset to 0 by the last block

__device__ __forceinline__ unsigned int min_key(float f) {
    int i = __float_as_int(f);
    i = i < 0 ? (i ^ 0x7FFFFFFF) : i;                 // total order as signed int
    return ~((unsigned int)i ^ 0x80000000u);          // flip to unsigned, invert
}
__device__ __forceinline__ float min_key_inv(unsigned int s) {
    int i = (int)(~s ^ 0x80000000u);
    i = i < 0 ? (i ^ 0x7FFFFFFF) : i;
    return __int_as_float(i);
}

__global__ __launch_bounds__(THREADS, 3) void chamfer_kernel(
    const float* __restrict__ x, const float* __restrict__ y,
    float* __restrict__ out) {
    // Two y-points per entry; one LDS.128 yields two packed f32x2 operands:
    //   sA[jp] = {nx_j0, nx_j1, ny_j0, ny_j1}
    //   sB[jp] = {nz_j0, nz_j1, pp_j0, pp_j1}
    // Padded by 1 entry for depth-1 prefetch overrun.
    __shared__ float4 sA[YP + 1], sB[YP + 1];
    __shared__ float sred[THREADS];
    __shared__ int s_last;

    const int yc   = blockIdx.x;
    const int xc   = blockIdx.y;
    const int dirb = blockIdx.z;
    const int dir  = dirb >> 3;
    const int b    = dirb & 7;

    const float* A  = dir ? y : x;
    const float* P  = dir ? x : y;
    const float* Ab = A + b * 3 * NP;
    const float* Pb = P + b * 3 * NP;

    const int tid = threadIdx.x;

    // Stage y-tile (YP=128 entries; first 128 threads).
    if (tid < YP) {
        int jp = tid;
        int g0 = yc * YT + 2 * jp;
        int g1 = g0 + 1;
        float px0 = Pb[g0],          px1 = Pb[g1];
        float py0 = Pb[NP + g0],     py1 = Pb[NP + g1];
        float pz0 = Pb[2 * NP + g0], pz1 = Pb[2 * NP + g1];
        float pp0 = fmaf(pz0, pz0, fmaf(py0, py0, px0 * px0));
        float pp1 = fmaf(pz1, pz1, fmaf(py1, py1, px1 * px1));
        sA[jp] = make_float4(-2.0f * px0, -2.0f * px1, -2.0f * py0, -2.0f * py1);
        sB[jp] = make_float4(-2.0f * pz0, -2.0f * pz1, pp0, pp1);
    }
    if (tid == 0) {  // init pad (prefetched but never used in a min)
        sA[YP] = make_float4(0.f, 0.f, 0.f, 0.f);
        sB[YP] = make_float4(0.f, 0.f, 0.f, 0.f);
    }
    __syncthreads();

    // Duplicated-packed x operands (loop invariant). 4 independent chains.
    unsigned long long axd[ILX], ayd[ILX], azd[ILX];
    float aa[ILX], mn[ILX];
#pragma unroll
    for (int k = 0; k < ILX; k++) {
        int gi = xc * XCHUNK + k * THREADS + tid;
        float ax = Ab[gi], ay = Ab[NP + gi], az = Ab[2 * NP + gi];
        PACK_F32X2(axd[k], ax, ax);
        PACK_F32X2(ayd[k], ay, ay);
        PACK_F32X2(azd[k], az, az);
        aa[k] = fmaf(az, az, fmaf(ay, ay, ax * ax));
        mn[k] = CUDART_INF_F;
    }

    // Depth-1 software pipeline: prefetch next jp while computing current.
    ulonglong2 va = *reinterpret_cast<const ulonglong2*>(&sA[0]);
    ulonglong2 vb = *reinterpret_cast<const ulonglong2*>(&sB[0]);
#pragma unroll 8
    for (int jp = 0; jp < YP; jp++) {
        ulonglong2 nva = *reinterpret_cast<const ulonglong2*>(&sA[jp + 1]);
        ulonglong2 nvb = *reinterpret_cast<const ulonglong2*>(&sB[jp + 1]);
        const unsigned long long mx = va.x;  // {nx0, nx1}
        const unsigned long long my = va.y;  // {ny0, ny1}
        const unsigned long long mz = vb.x;  // {nz0, nz1}
        const unsigned long long pp = vb.y;  // {pp0, pp1}
#pragma unroll
        for (int k = 0; k < ILX; k++) {
            unsigned long long t;
            FMA_F32X2(t, axd[k], mx, pp);
            FMA_F32X2(t, ayd[k], my, t);
            FMA_F32X2(t, azd[k], mz, t);
            float lo, hi;
            UNPACK_F32X2(lo, hi, t);
            mn[k] = fminf(mn[k], fminf(lo, hi));  // short carried chain
        }
        va = nva;
        vb = nvb;
    }

    unsigned int* gm = g_min + dirb * NP;
#pragma unroll
    for (int k = 0; k < ILX; k++) {
        int gi = xc * XCHUNK + k * THREADS + tid;
        atomicMax(&gm[gi], min_key(aa[k] + mn[k]));  // RED.MAX, float-min
    }

    // ---- last-done-block fold (threadFenceReduction pattern) ----
    __threadfence();  // order this block's REDs before the counter bump
    if (tid == 0) {
        int prev = atomicAdd(&g_count, 1);
        s_last = (prev == NBLOCKS - 1) ? 1 : 0;
    }
    __syncthreads();
    if (!s_last) return;

    __threadfence();  // acquire side: see all other blocks' REDs

    // Sweep all 64K keys: 64 coalesced uint4 per thread, decode+sum,
    // and reset to 0 for the next graph replay.
    float s = 0.0f;
#pragma unroll 4
    for (int i = tid; i < NKEY / 4; i += THREADS) {
        uint4 v = *reinterpret_cast<const uint4*>(&g_min[i * 4]);
        *reinterpret_cast<uint4*>(&g_min[i * 4]) = make_uint4(0u, 0u, 0u, 0u);
        s += min_key_inv(v.x) + min_key_inv(v.y) +
             min_key_inv(v.z) + min_key_inv(v.w);
    }
    sred[tid] = s;
    __syncthreads();
    for (int w = THREADS / 2; w > 0; w >>= 1) {
        if (tid < w) sred[tid] += sred[tid + w];
        __syncthreads();
    }
    if (tid == 0) {
        out[0] = sred[0] / (float)(NB * NP);
        g_count = 0;  // reset for next graph replay
    }
}

extern "C" void kernel_launch(void* const* d_in, const int* in_sizes, int n_in,
                              void* d_out, int out_size) {
    const float* x = (const float*)d_in[0];
    const float* y = (const float*)d_in[1];
    float* out = (float*)d_out;

    dim3 grid(YC, XC, NDB);  // 16 x 4 x 16 = 1024 blocks
    chamfer_kernel<<<grid, THREADS>>>(x, y, out);
}

// round 16
// speedup vs baseline: 1.1868x; 1.1868x over previous
#include <cuda_runtime.h>
#include <math_constants.h>

#define NB 8
#define NP 4096
#define THREADS 256
#define ILX 4                        // scalar x-points per thread (duplicated-packed)
#define XCHUNK (THREADS * ILX)       // 1024
#define XC (NP / XCHUNK)             // 4
#define YT 128
#define YP (YT / 2)                  // 64 j-pairs
#define YC (NP / YT)                 // 32
#define NDB (2 * NB)                 // 16 (dir, batch) pairs
#define RBLOCKS 64                   // reduce: 64 blocks x 256 thr x 4 vals

#define FMA_F32X2(d, a, b, c) \
    asm("fma.rn.f32x2 %0, %1, %2, %3;" : "=l"(d) : "l"(a), "l"(b), "l"(c))
#define PACK_F32X2(out, lo, hi) \
    asm("mov.b64 %0, {%1, %2};" : "=l"(out) : "f"(lo), "f"(hi))
#define UNPACK_F32X2(lo, hi, in) \
    asm("mov.b64 {%0, %1}, %2;" : "=f"(lo), "=f"(hi) : "l"(in))

// Per-(dir,batch,point) running min, as a transformed unsigned key where
// LARGER unsigned == SMALLER float, and 0 == "+inf". So atomicMax implements
// float-min and BSS zero-init is the correct initial state. The reduce
// kernel resets slots to 0 after consuming them -> every graph replay sees
// the same initial state (deterministic, no init kernel).
__device__ unsigned int g_min[NDB * NP];    // 256 KB
__device__ float g_psum[RBLOCKS];
__device__ int   g_count;                   // reset to 0 by last reduce block

__device__ __forceinline__ unsigned int min_key(float f) {
    int i = __float_as_int(f);
    i = i < 0 ? (i ^ 0x7FFFFFFF) : i;                 // total order as signed int
    return ~((unsigned int)i ^ 0x80000000u);          // flip to unsigned, invert
}
__device__ __forceinline__ float min_key_inv(unsigned int s) {
    int i = (int)(~s ^ 0x80000000u);
    i = i < 0 ? (i ^ 0x7FFFFFFF) : i;
    return __int_as_float(i);
}

__global__ __launch_bounds__(THREADS, 3) void chamfer_kernel(
    const float* __restrict__ x, const float* __restrict__ y) {
    // Two y-points per entry; one LDS.128 yields two packed f32x2 operands:
    //   sA[jp] = {nx_j0, nx_j1, ny_j0, ny_j1}
    //   sB[jp] = {nz_j0, nz_j1, pp_j0, pp_j1}
    // Padded by 1 entry for depth-1 prefetch overrun.
    __shared__ float4 sA[YP + 1], sB[YP + 1];

    const int yc   = blockIdx.x;
    const int xc   = blockIdx.y;
    const int dirb = blockIdx.z;
    const int dir  = dirb >> 3;
    const int b    = dirb & 7;

    const float* A  = dir ? y : x;
    const float* P  = dir ? x : y;
    const float* Ab = A + b * 3 * NP;
    const float* Pb = P + b * 3 * NP;

    const int tid = threadIdx.x;

    // Stage y-tile (YP=64 entries; first 64 threads).
    if (tid < YP) {
        int jp = tid;
        int g0 = yc * YT + 2 * jp;
        int g1 = g0 + 1;
        float px0 = Pb[g0],          px1 = Pb[g1];
        float py0 = Pb[NP + g0],     py1 = Pb[NP + g1];
        float pz0 = Pb[2 * NP + g0], pz1 = Pb[2 * NP + g1];
        float pp0 = fmaf(pz0, pz0, fmaf(py0, py0, px0 * px0));
        float pp1 = fmaf(pz1, pz1, fmaf(py1, py1, px1 * px1));
        sA[jp] = make_float4(-2.0f * px0, -2.0f * px1, -2.0f * py0, -2.0f * py1);
        sB[jp] = make_float4(-2.0f * pz0, -2.0f * pz1, pp0, pp1);
    }
    if (tid == 0) {  // init pad (prefetched but never used in a min)
        sA[YP] = make_float4(0.f, 0.f, 0.f, 0.f);
        sB[YP] = make_float4(0.f, 0.f, 0.f, 0.f);
    }
    __syncthreads();

    // Duplicated-packed x operands (loop invariant). 4 independent chains.
    unsigned long long axd[ILX], ayd[ILX], azd[ILX];
    float aa[ILX], mn[ILX];
#pragma unroll
    for (int k = 0; k < ILX; k++) {
        int gi = xc * XCHUNK + k * THREADS + tid;
        float ax = Ab[gi], ay = Ab[NP + gi], az = Ab[2 * NP + gi];
        PACK_F32X2(axd[k], ax, ax);
        PACK_F32X2(ayd[k], ay, ay);
        PACK_F32X2(azd[k], az, az);
        aa[k] = fmaf(az, az, fmaf(ay, ay, ax * ax));
        mn[k] = CUDART_INF_F;
    }

    // Depth-1 software pipeline: prefetch next jp while computing current.
    ulonglong2 va = *reinterpret_cast<const ulonglong2*>(&sA[0]);
    ulonglong2 vb = *reinterpret_cast<const ulonglong2*>(&sB[0]);
#pragma unroll 8
    for (int jp = 0; jp < YP; jp++) {
        ulonglong2 nva = *reinterpret_cast<const ulonglong2*>(&sA[jp + 1]);
        ulonglong2 nvb = *reinterpret_cast<const ulonglong2*>(&sB[jp + 1]);
        const unsigned long long mx = va.x;  // {nx0, nx1}
        const unsigned long long my = va.y;  // {ny0, ny1}
        const unsigned long long mz = vb.x;  // {nz0, nz1}
        const unsigned long long pp = vb.y;  // {pp0, pp1}
#pragma unroll
        for (int k = 0; k < ILX; k++) {
            unsigned long long t;
            FMA_F32X2(t, axd[k], mx, pp);
            FMA_F32X2(t, ayd[k], my, t);
            FMA_F32X2(t, azd[k], mz, t);
            float lo, hi;
            UNPACK_F32X2(lo, hi, t);
            mn[k] = fminf(mn[k], fminf(lo, hi));  // short carried chain
        }
        va = nva;
        vb = nvb;
    }

    unsigned int* gm = g_min + dirb * NP;
#pragma unroll
    for (int k = 0; k < ILX; k++) {
        int gi = xc * XCHUNK + k * THREADS + tid;
        atomicMax(&gm[gi], min_key(aa[k] + mn[k]));  // RED.MAX, float-min
    }
}

// Fused reduce: decode + sum 64K keys (coalesced uint4), reset slots to 0
// for the next replay; last-done block folds partials and writes the scalar.
__global__ __launch_bounds__(256) void reduce_kernel(float* __restrict__ out) {
    __shared__ float sred[256];
    __shared__ int s_last;
    const int tid = threadIdx.x;
    const int base = (blockIdx.x * 256 + tid) * 4;  // 4 consecutive keys

    uint4 v = *reinterpret_cast<const uint4*>(&g_min[base]);
    *reinterpret_cast<uint4*>(&g_min[base]) = make_uint4(0u, 0u, 0u, 0u);

    float s = min_key_inv(v.x) + min_key_inv(v.y) +
              min_key_inv(v.z) + min_key_inv(v.w);

    sred[tid] = s;
    __syncthreads();
    for (int w = 128; w > 0; w >>= 1) {
        if (tid < w) sred[tid] += sred[tid + w];
        __syncthreads();
    }
    if (tid == 0) {
        g_psum[blockIdx.x] = sred[0];
        __threadfence();
        int prev = atomicAdd(&g_count, 1);
        s_last = (prev == gridDim.x - 1) ? 1 : 0;
    }
    __syncthreads();

    if (s_last) {
        float t = (tid < RBLOCKS) ? g_psum[tid] : 0.0f;
        sred[tid] = t;
        __syncthreads();
        for (int w = 128; w > 0; w >>= 1) {
            if (tid < w) sred[tid] += sred[tid + w];
            __syncthreads();
        }
        if (tid == 0) {
            out[0] = sred[0] / (float)(NB * NP);
            g_count = 0;  // reset for next graph replay
        }
    }
}

extern "C" void kernel_launch(void* const* d_in, const int* in_sizes, int n_in,
                              void* d_out, int out_size) {
    const float* x = (const float*)d_in[0];
    const float* y = (const float*)d_in[1];
    float* out = (float*)d_out;

    dim3 grid(YC, XC, NDB);  // 32 x 4 x 16 = 2048 blocks
    chamfer_kernel<<<grid, THREADS>>>(x, y);
    reduce_kernel<<<RBLOCKS, 256>>>(out);
}